// round 7
// baseline (speedup 1.0000x reference)
#include <cuda_runtime.h>
#include <math.h>
#include <stdint.h>

// GNN on complete per-scene digraphs: B=64 scenes, N=128 nodes.
// segment_mean at node d = (scene_sum(h) - h[d]) / 127.
// R7: NO clusters. grid=128: CTAs (2b, 2b+1) BOTH compute the full scene b
// (redundant compute), each writes its own half of node outputs. Zero
// cross-CTA communication. 1024 thr/CTA (8 thr/node), occ 50%.
//  - out = relu(b + cs@Ws - s@Ws); Ws = W/127 prescaled in smem
//  - node-term GEMV in packed fma.rn.f32x2
//  - colsum fused into emit: scalar warp butterfly + lane0 atomics
//  - 2 __syncthreads per layer

#define NODES    128
#define SCENES   64
#define THREADS  1024
#define STRIDE   77          // coprime with 32 -> conflict-free column access
#define INV127   (1.0f/127.0f)

typedef unsigned long long u64;

// smem layout (float indices)
#define S_W1s    0            // 5*64  (W1/127)
#define S_W1s128 320          // 5*64  (W1*128/127)
#define S_B1     640          // 64
#define S_W2s    704          // 75*64
#define S_B2     5504         // 64
#define S_W3s    5568         // 64*32
#define S_B3     7616         // 32
#define S_W4s    7648         // 32*16
#define S_B4     8160         // 16
#define S_WNs    8176         // 16*2
#define S_BN     8208         // 2 (+2)
#define S_WG1    8212         // 16*8
#define S_BG1    8340         // 8
#define S_WG2    8348         // 8
#define S_BG2    8356         // 1 (+3)
#define S_A      8360         // 128*77
#define S_BUF    18216        // 128*77
#define S_CS2    28072        // 80: [0..63]=h1 csl, [64..74]=info csl
#define S_CS3    28152        // 64
#define S_CS4    28216        // 32
#define S_CS5    28248        // 16
#define S_BASE   28264        // 64
#define S_PART   28328        // 352 (info colsum partials)
#define S_TOT    28680
#define SMEM_BYTES (S_TOT * 4)   // 114720 B

// ---- packed f32x2 helpers ----
__device__ __forceinline__ u64 pack2(float lo, float hi) {
    u64 r; asm("mov.b64 %0, {%1, %2};" : "=l"(r) : "f"(lo), "f"(hi)); return r;
}
__device__ __forceinline__ void unpack2(u64 v, float& lo, float& hi) {
    asm("mov.b64 {%0, %1}, %2;" : "=f"(lo), "=f"(hi) : "l"(v));
}
__device__ __forceinline__ u64 fma2(u64 a, u64 b, u64 c) {
    u64 r; asm("fma.rn.f32x2 %0, %1, %2, %3;" : "=l"(r) : "l"(a), "l"(b), "l"(c)); return r;
}

// packed node term: acc2[v] accumulates columns (q*JT+2v, q*JT+2v+1)
template<int IN, int OUT, int JT>
__device__ __forceinline__ void nodeterm2(const float* __restrict__ S, int off,
                                          const float* __restrict__ Ws,
                                          u64* __restrict__ acc2, int n, int q) {
    const int j0 = q * JT;
    #pragma unroll
    for (int v = 0; v < JT / 2; v++) acc2[v] = 0ull;
    const float* srow = S + n * STRIDE + off;
    for (int k = 0; k < IN; k++) {
        float a = srow[k];
        u64 aa = pack2(a, a);
        if constexpr (JT == 8) {
            const ulonglong2* wr = reinterpret_cast<const ulonglong2*>(Ws + k * OUT + j0);
            ulonglong2 w0 = wr[0], w1 = wr[1];
            acc2[0] = fma2(aa, w0.x, acc2[0]);
            acc2[1] = fma2(aa, w0.y, acc2[1]);
            acc2[2] = fma2(aa, w1.x, acc2[2]);
            acc2[3] = fma2(aa, w1.y, acc2[3]);
        } else if constexpr (JT == 4) {
            const ulonglong2* wr = reinterpret_cast<const ulonglong2*>(Ws + k * OUT + j0);
            ulonglong2 w0 = wr[0];
            acc2[0] = fma2(aa, w0.x, acc2[0]);
            acc2[1] = fma2(aa, w0.y, acc2[1]);
        } else {
            const u64* wr = reinterpret_cast<const u64*>(Ws + k * OUT + j0);
            acc2[0] = fma2(aa, wr[0], acc2[0]);
        }
    }
}

// One layer. Sequence per layer (2 barriers):
//   base[j] = bias[j] + cs_prev @ Ws   (first 4*OUT threads)
//   nodeterm (all threads)             -- independent of base
//   __syncthreads
//   emit: act = relu(base - acc) -> D; warp butterfly; lane0 atomics -> cs_next
//   __syncthreads
template<int IN, int OUT, int JT>
__device__ __forceinline__ void layer_run(
    float* __restrict__ sm, const float* __restrict__ Ssrc, int soff,
    float* __restrict__ D,
    const float* __restrict__ cs_prev, float* __restrict__ cs_next,
    const float* __restrict__ Wb, const float* __restrict__ Wn_,
    const float* __restrict__ bias,
    int tid, int lane, int n, int q)
{
    float* base = sm + S_BASE;

    if (tid < 4 * OUT) {
        const int j = tid >> 2, p = tid & 3;
        float s = 0.f;
        for (int k = p; k < IN; k += 4) s += cs_prev[k] * Wb[k * OUT + j];
        s += __shfl_xor_sync(0xffffffffu, s, 1);
        s += __shfl_xor_sync(0xffffffffu, s, 2);
        if (p == 0) base[j] = bias[j] + s;
    }

    u64 acc2[JT / 2];
    nodeterm2<IN, OUT, JT>(Ssrc, soff, Wn_, acc2, n, q);

    __syncthreads();

    const int j0 = q * JT;
    float r[JT];
    #pragma unroll
    for (int v = 0; v < JT / 2; v++) {
        float lo, hi; unpack2(acc2[v], lo, hi);
        r[2 * v]     = fmaxf(base[j0 + 2 * v]     - lo, 0.f);
        r[2 * v + 1] = fmaxf(base[j0 + 2 * v + 1] - hi, 0.f);
    }
    float* drow = D + n * STRIDE + j0;
    #pragma unroll
    for (int v = 0; v < JT; v++) drow[v] = r[v];
    #pragma unroll
    for (int off = 1; off < 32; off <<= 1) {
        #pragma unroll
        for (int v = 0; v < JT; v++)
            r[v] += __shfl_xor_sync(0xffffffffu, r[v], off);
    }
    if (lane == 0) {
        #pragma unroll
        for (int v = 0; v < JT; v++) atomicAdd(&cs_next[j0 + v], r[v]);
    }
    __syncthreads();
}

__global__ __launch_bounds__(THREADS, 1)
void gnn_scene_kernel(const float* __restrict__ obj_info,
                      const float* __restrict__ W1, const float* __restrict__ b1,
                      const float* __restrict__ W2, const float* __restrict__ b2,
                      const float* __restrict__ W3, const float* __restrict__ b3,
                      const float* __restrict__ W4, const float* __restrict__ b4,
                      const float* __restrict__ Wn, const float* __restrict__ bn,
                      const float* __restrict__ Wg1, const float* __restrict__ bg1,
                      const float* __restrict__ Wg2, const float* __restrict__ bg2,
                      float* __restrict__ out) {
    extern __shared__ float sm[];
    const int tid  = threadIdx.x;
    const int lane = tid & 31;
    const int b    = blockIdx.x >> 1;
    const int rank = blockIdx.x & 1;     // which half of nodes this CTA writes
    const int n = tid & (NODES - 1);     // node 0..127
    const int q = tid >> 7;              // 0..7

    // ---- load + prescale weights ----
    for (int i = tid; i < 5 * 64; i += THREADS) {
        float w = W1[i];
        sm[S_W1s + i]    = w * INV127;
        sm[S_W1s128 + i] = w * (128.0f * INV127);
    }
    #define CPYS(dst, src, cnt) \
        for (int i = tid; i < (cnt); i += THREADS) sm[(dst) + i] = src[i] * INV127;
    #define CPY(dst, src, cnt) \
        for (int i = tid; i < (cnt); i += THREADS) sm[(dst) + i] = src[i];
    CPYS(S_W2s, W2, 75*64);  CPY(S_B2, b2, 64);
    CPYS(S_W3s, W3, 64*32);  CPY(S_B3, b3, 32);
    CPYS(S_W4s, W4, 32*16);  CPY(S_B4, b4, 16);
    CPYS(S_WNs, Wn, 16*2);   CPY(S_BN, bn, 2);
    CPY(S_B1, b1, 64);
    CPY(S_WG1, Wg1, 16*8);   CPY(S_BG1, bg1, 8);
    CPY(S_WG2, Wg2, 8);      CPY(S_BG2, bg2, 1);
    #undef CPYS
    #undef CPY

    // ---- load FULL scene info (128 x 11) into A cols 64..74 ----
    {
        const float* src = obj_info + (size_t)b * NODES * 11;
        for (int i = tid; i < NODES * 11; i += THREADS) {
            int r = i / 11, c = i % 11;
            sm[S_A + r * STRIDE + 64 + c] = src[i];
        }
    }
    // zero atomic-accumulated csl slots (176 floats)
    if (tid < 64)        sm[S_CS2 + tid] = 0.f;
    else if (tid < 128)  sm[S_CS3 + tid - 64] = 0.f;
    else if (tid < 160)  sm[S_CS4 + tid - 128] = 0.f;
    else if (tid < 176)  sm[S_CS5 + tid - 160] = 0.f;
    __syncthreads();

    float* A  = sm + S_A;
    float* Bb = sm + S_BUF;

    // ---- info colsum (11 cols x 128 rows) -> cs2[64..74] ----
    if (tid < 11 * 32) {
        int c = tid % 11, p = tid / 11;
        float s = 0.f;
        #pragma unroll
        for (int r = 0; r < 4; r++) s += A[(p * 4 + r) * STRIDE + 64 + c];
        sm[S_PART + p * 11 + c] = s;
    }
    __syncthreads();
    if (tid < 11) {
        float s = 0.f;
        #pragma unroll
        for (int p = 0; p < 32; p++) s += sm[S_PART + p * 11 + tid];
        sm[S_CS2 + 64 + tid] = s;
    }
    __syncthreads();

    // L1 (edge): info[:, :5] -> h1 (A cols 0..63); cs_next -> cs2[0..63]
    layer_run<5, 64, 8>(sm, A, 64, A, sm + S_CS2 + 64, sm + S_CS2,
                        sm + S_W1s, sm + S_W1s128, sm + S_B1, tid, lane, n, q);

    // L2: h75 (A cols 0..74) -> h2 (Bb cols 0..63); cs_next -> cs3
    layer_run<75, 64, 8>(sm, A, 0, Bb, sm + S_CS2, sm + S_CS3,
                         sm + S_W2s, sm + S_W2s, sm + S_B2, tid, lane, n, q);

    // L3: h2 -> h3 (A cols 0..31); cs_next -> cs4
    layer_run<64, 32, 4>(sm, Bb, 0, A, sm + S_CS3, sm + S_CS4,
                         sm + S_W3s, sm + S_W3s, sm + S_B3, tid, lane, n, q);

    // L4: h3 -> h4 (Bb cols 0..15); cs_next -> cs5
    layer_run<32, 16, 2>(sm, A, 0, Bb, sm + S_CS4, sm + S_CS5,
                         sm + S_W4s, sm + S_W4s, sm + S_B4, tid, lane, n, q);

    // ---- node head: out = bn + cs5@WNs - h4_n@WNs (no relu) ----
    {
        float* base = sm + S_BASE;
        if (tid < 8) {
            int j = tid >> 2, p = tid & 3;
            float s = 0.f;
            for (int k = p; k < 16; k += 4) s += sm[S_CS5 + k] * sm[S_WNs + k * 2 + j];
            s += __shfl_xor_sync(0xffu, s, 1);
            s += __shfl_xor_sync(0xffu, s, 2);
            if (p == 0) base[j] = sm[S_BN + j] + s;
        }
        float accn = 0.f;
        if (q < 2) {
            const float* srow = Bb + n * STRIDE;
            #pragma unroll
            for (int k = 0; k < 16; k++) accn += srow[k] * sm[S_WNs + k * 2 + q];
        }
        __syncthreads();
        // write only this CTA's half of the nodes
        if (q < 2 && (n >> 6) == rank) {
            size_t gnode = (size_t)b * NODES + n;
            out[64 + gnode * 2 + q] = base[q] - accn;
        }
    }

    // ---- scene head (identical in both CTAs; rank 0 writes) ----
    if (rank == 0 && tid == 0) {
        float scene[16];
        #pragma unroll
        for (int k = 0; k < 16; k++) scene[k] = sm[S_CS5 + k] * (1.0f / NODES);
        float z = sm[S_BG2];
        #pragma unroll
        for (int o = 0; o < 8; o++) {
            float g = sm[S_BG1 + o];
            #pragma unroll
            for (int k = 0; k < 16; k++) g += scene[k] * sm[S_WG1 + k * 8 + o];
            g = fmaxf(g, 0.f);
            z += g * sm[S_WG2 + o];
        }
        out[b] = 1.0f / (1.0f + expf(-z));
    }
}

extern "C" void kernel_launch(void* const* d_in, const int* in_sizes, int n_in,
                              void* d_out, int out_size) {
    const float* obj = (const float*)d_in[0];
    const float* W1  = (const float*)d_in[1];
    const float* b1  = (const float*)d_in[2];
    const float* W2  = (const float*)d_in[3];
    const float* b2  = (const float*)d_in[4];
    const float* W3  = (const float*)d_in[5];
    const float* b3  = (const float*)d_in[6];
    const float* W4  = (const float*)d_in[7];
    const float* b4  = (const float*)d_in[8];
    const float* Wn  = (const float*)d_in[9];
    const float* bn  = (const float*)d_in[10];
    const float* Wg1 = (const float*)d_in[11];
    const float* bg1 = (const float*)d_in[12];
    const float* Wg2 = (const float*)d_in[13];
    const float* bg2 = (const float*)d_in[14];
    // d_in[15]=src, d_in[16]=dst: complete graph, exploited analytically.

    cudaFuncSetAttribute(gnn_scene_kernel,
                         cudaFuncAttributeMaxDynamicSharedMemorySize, SMEM_BYTES);
    gnn_scene_kernel<<<SCENES * 2, THREADS, SMEM_BYTES>>>(
        obj, W1, b1, W2, b2, W3, b3, W4, b4, Wn, bn, Wg1, bg1, Wg2, bg2,
        (float*)d_out);
}

// round 9
// speedup vs baseline: 1.2135x; 1.2135x over previous
#include <cuda_runtime.h>
#include <math.h>
#include <stdint.h>

// GNN on complete per-scene digraphs: B=64 scenes, N=128 nodes.
// segment_mean at node d = (scene_sum(h) - h[d]) / 127.
// R9 (= R8 resubmit; prior bench was an infra failure):
// 2-CTA cluster/scene (64 nodes/CTA, NO redundant work), 1024 thr/CTA
// = 16 threads/node (JT 4/4/2/1). out = relu(b + cs@Ws - s@Ws), Ws=W/127.
//  - base = b + bp_local + bp_peer; bp exchange = pull pattern
//    (arrive -> nodeterm overlaps -> wait -> DSMEM pull), ping-pong slots
//  - node-term GEMV: packed fma.rn.f32x2, float4 srow loads (STRIDE=84)
//  - colsum fused into emit: warp butterfly + lane0 atomics
//  - per layer: 1 cluster barrier + 2 __syncthreads

#define NODES    128
#define LOCALN   64
#define SCENES   64
#define THREADS  1024
#define STRIDE   84          // 16B-aligned rows
#define INV127   (1.0f/127.0f)

typedef unsigned long long u64;

// smem layout (float indices)
#define S_W1s    0            // 5*64  (W1/127)
#define S_W1s128 320          // 5*64  (W1*128/127)
#define S_B1     640          // 64
#define S_W2s    704          // 75*64
#define S_B2     5504         // 64
#define S_W3s    5568         // 64*32
#define S_B3     7616         // 32
#define S_W4s    7648         // 32*16
#define S_B4     8160         // 16
#define S_WNs    8176         // 16*2
#define S_BN     8208         // 2 (+2)
#define S_WG1    8212         // 16*8
#define S_BG1    8340         // 8
#define S_WG2    8348         // 8
#define S_BG2    8356         // 1 (+3)
#define S_A      8360         // 64*84
#define S_BUF    13736        // 64*84
#define S_CS2    19112        // 80: [0..63] h1 csl (atomics), [64..74] info csl
#define S_CS3    19192        // 64
#define S_CS4    19256        // 32
#define S_CS5    19288        // 16
#define S_SCENEB 19304        // 16 (peer cs5)
#define S_BASE   19320        // 64
#define S_BP     19384        // 2 slots x 64
#define S_PART   19512        // 176
#define S_TOT    19688
#define SMEM_BYTES (S_TOT * 4)   // 78752 B

__device__ __forceinline__ uint32_t smem_u32(const void* p) {
    uint32_t a;
    asm("{ .reg .u64 t; cvta.to.shared.u64 t, %1; cvt.u32.u64 %0, t; }"
        : "=r"(a) : "l"(p));
    return a;
}
__device__ __forceinline__ float ld_peer_f32(uint32_t la, uint32_t peer) {
    uint32_t ra;
    asm("mapa.shared::cluster.u32 %0, %1, %2;" : "=r"(ra) : "r"(la), "r"(peer));
    float v;
    asm volatile("ld.shared::cluster.f32 %0, [%1];" : "=f"(v) : "r"(ra));
    return v;
}
#define CLUSTER_ARRIVE() asm volatile("barrier.cluster.arrive.aligned;" ::: "memory")
#define CLUSTER_WAIT()   asm volatile("barrier.cluster.wait.aligned;"   ::: "memory")

// ---- packed f32x2 helpers ----
__device__ __forceinline__ u64 pack2(float lo, float hi) {
    u64 r; asm("mov.b64 %0, {%1, %2};" : "=l"(r) : "f"(lo), "f"(hi)); return r;
}
__device__ __forceinline__ void unpack2(u64 v, float& lo, float& hi) {
    asm("mov.b64 {%0, %1}, %2;" : "=f"(lo), "=f"(hi) : "l"(v));
}
__device__ __forceinline__ u64 fma2(u64 a, u64 b, u64 c) {
    u64 r; asm("fma.rn.f32x2 %0, %1, %2, %3;" : "=l"(r) : "l"(a), "l"(b), "l"(c)); return r;
}

// process one k for the packed node term
template<int OUT, int JT>
__device__ __forceinline__ void nt_step(float a, const float* __restrict__ Ws,
                                        int k, int j0, u64* acc2, float& acc1) {
    if constexpr (JT == 4) {
        u64 aa = pack2(a, a);
        ulonglong2 w = *reinterpret_cast<const ulonglong2*>(Ws + k * OUT + j0);
        acc2[0] = fma2(aa, w.x, acc2[0]);
        acc2[1] = fma2(aa, w.y, acc2[1]);
    } else if constexpr (JT == 2) {
        u64 aa = pack2(a, a);
        u64 w = *reinterpret_cast<const u64*>(Ws + k * OUT + j0);
        acc2[0] = fma2(aa, w, acc2[0]);
    } else {
        acc1 += a * Ws[k * OUT + j0];
    }
}

// One GCN layer. Entry: cs_prev (local colsum) ready, CTA-synced.
// Exit: D holds activations, cs_next holds local colsum of D, CTA-synced.
template<int IN, int OUT, int JT>
__device__ __forceinline__ void layer_run(
    float* __restrict__ sm, const float* __restrict__ Ssrc, int soff,
    float* __restrict__ D,
    const float* __restrict__ cs_prev, float* __restrict__ cs_next,
    const float* __restrict__ Wb, const float* __restrict__ Wn_,
    const float* __restrict__ bias,
    int slot, int tid, int lane, int n, int q, uint32_t peer, uint32_t smbase)
{
    float* base = sm + S_BASE;
    float* bp   = sm + S_BP + slot * 64;

    // base-partial on LOCAL colsum: 4 threads per output column
    if (tid < 4 * OUT) {
        const int j = tid >> 2, p = tid & 3;
        float s = 0.f;
        for (int k = p; k < IN; k += 4) s += cs_prev[k] * Wb[k * OUT + j];
        s += __shfl_xor_sync(0xffffffffu, s, 1);
        s += __shfl_xor_sync(0xffffffffu, s, 2);
        if (p == 0) bp[j] = s;
    }
    CLUSTER_ARRIVE();

    // node term: acc[j] = sum_k s[n][k] * Ws[k][j0+j]  (overlaps peer skew)
    const int j0 = q * JT;
    u64 acc2[JT == 4 ? 2 : 1];
    float acc1 = 0.f;
    #pragma unroll
    for (int v = 0; v < (JT == 4 ? 2 : 1); v++) acc2[v] = 0ull;
    const float* srow = Ssrc + n * STRIDE + soff;
    {
        constexpr int KB = IN / 4;
        const float4* s4 = reinterpret_cast<const float4*>(srow);
        for (int kb = 0; kb < KB; kb++) {
            float4 a4 = s4[kb];
            nt_step<OUT, JT>(a4.x, Wn_, 4 * kb + 0, j0, acc2, acc1);
            nt_step<OUT, JT>(a4.y, Wn_, 4 * kb + 1, j0, acc2, acc1);
            nt_step<OUT, JT>(a4.z, Wn_, 4 * kb + 2, j0, acc2, acc1);
            nt_step<OUT, JT>(a4.w, Wn_, 4 * kb + 3, j0, acc2, acc1);
        }
        #pragma unroll
        for (int k = KB * 4; k < IN; k++)
            nt_step<OUT, JT>(srow[k], Wn_, k, j0, acc2, acc1);
    }

    CLUSTER_WAIT();   // cluster-wide barrier: bp (both CTAs) ready

    // combine: base = bias + bp_local + bp_peer
    if (tid < OUT) {
        uint32_t la = smbase + (uint32_t)(S_BP + slot * 64 + tid) * 4u;
        base[tid] = bias[tid] + bp[tid] + ld_peer_f32(la, peer);
    }
    __syncthreads();

    // emit + fused colsum
    float r[JT];
    if constexpr (JT == 4) {
        float l0, h0, l1, h1;
        unpack2(acc2[0], l0, h0); unpack2(acc2[1], l1, h1);
        r[0] = fmaxf(base[j0 + 0] - l0, 0.f);
        r[1] = fmaxf(base[j0 + 1] - h0, 0.f);
        r[2] = fmaxf(base[j0 + 2] - l1, 0.f);
        r[3] = fmaxf(base[j0 + 3] - h1, 0.f);
        float4 st = make_float4(r[0], r[1], r[2], r[3]);
        *reinterpret_cast<float4*>(D + n * STRIDE + j0) = st;
    } else if constexpr (JT == 2) {
        float l0, h0;
        unpack2(acc2[0], l0, h0);
        r[0] = fmaxf(base[j0 + 0] - l0, 0.f);
        r[1] = fmaxf(base[j0 + 1] - h0, 0.f);
        *reinterpret_cast<float2*>(D + n * STRIDE + j0) = make_float2(r[0], r[1]);
    } else {
        r[0] = fmaxf(base[j0] - acc1, 0.f);
        D[n * STRIDE + j0] = r[0];
    }
    #pragma unroll
    for (int off = 1; off < 32; off <<= 1) {
        #pragma unroll
        for (int v = 0; v < JT; v++)
            r[v] += __shfl_xor_sync(0xffffffffu, r[v], off);
    }
    if (lane == 0) {
        #pragma unroll
        for (int v = 0; v < JT; v++) atomicAdd(&cs_next[j0 + v], r[v]);
    }
    __syncthreads();
}

__global__ __launch_bounds__(THREADS, 1) __cluster_dims__(2, 1, 1)
void gnn_scene_kernel(const float* __restrict__ obj_info,
                      const float* __restrict__ W1, const float* __restrict__ b1,
                      const float* __restrict__ W2, const float* __restrict__ b2,
                      const float* __restrict__ W3, const float* __restrict__ b3,
                      const float* __restrict__ W4, const float* __restrict__ b4,
                      const float* __restrict__ Wn, const float* __restrict__ bn,
                      const float* __restrict__ Wg1, const float* __restrict__ bg1,
                      const float* __restrict__ Wg2, const float* __restrict__ bg2,
                      float* __restrict__ out) {
    extern __shared__ float sm[];
    const int tid  = threadIdx.x;
    const int lane = tid & 31;
    const int b    = blockIdx.x >> 1;
    const uint32_t rank = blockIdx.x & 1;
    const uint32_t peer = rank ^ 1u;
    const int n = tid & (LOCALN - 1);   // local node 0..63
    const int q = tid >> 6;             // 0..15
    const uint32_t smbase = smem_u32(sm);

    // ---- load + prescale weights ----
    for (int i = tid; i < 5 * 64; i += THREADS) {
        float w = W1[i];
        sm[S_W1s + i]    = w * INV127;
        sm[S_W1s128 + i] = w * (128.0f * INV127);
    }
    #define CPYS(dst, src, cnt) \
        for (int i = tid; i < (cnt); i += THREADS) sm[(dst) + i] = src[i] * INV127;
    #define CPY(dst, src, cnt) \
        for (int i = tid; i < (cnt); i += THREADS) sm[(dst) + i] = src[i];
    CPYS(S_W2s, W2, 75*64);  CPY(S_B2, b2, 64);
    CPYS(S_W3s, W3, 64*32);  CPY(S_B3, b3, 32);
    CPYS(S_W4s, W4, 32*16);  CPY(S_B4, b4, 16);
    CPYS(S_WNs, Wn, 16*2);   CPY(S_BN, bn, 2);
    CPY(S_B1, b1, 64);
    CPY(S_WG1, Wg1, 16*8);   CPY(S_BG1, bg1, 8);
    CPY(S_WG2, Wg2, 8);      CPY(S_BG2, bg2, 1);
    #undef CPYS
    #undef CPY

    // ---- load this CTA's 64 rows of info[b] into A cols 64..74 ----
    {
        const float* src = obj_info + ((size_t)b * NODES + rank * LOCALN) * 11;
        for (int i = tid; i < LOCALN * 11; i += THREADS) {
            int r = i / 11, c = i % 11;
            sm[S_A + r * STRIDE + 64 + c] = src[i];
        }
    }
    // zero atomic-accumulated local colsum slots
    if (tid < 64)        sm[S_CS2 + tid] = 0.f;
    else if (tid < 128)  sm[S_CS3 + tid - 64] = 0.f;
    else if (tid < 160)  sm[S_CS4 + tid - 128] = 0.f;
    else if (tid < 176)  sm[S_CS5 + tid - 160] = 0.f;
    __syncthreads();

    float* A  = sm + S_A;
    float* Bb = sm + S_BUF;

    // ---- info colsum (11 cols x 64 rows) -> cs2[64..74] ----
    if (tid < 11 * 16) {
        int c = tid % 11, p = tid / 11;
        float s = 0.f;
        #pragma unroll
        for (int r = 0; r < 4; r++) s += A[(p * 4 + r) * STRIDE + 64 + c];
        sm[S_PART + p * 11 + c] = s;
    }
    __syncthreads();
    if (tid < 11) {
        float s = 0.f;
        #pragma unroll
        for (int p = 0; p < 16; p++) s += sm[S_PART + p * 11 + tid];
        sm[S_CS2 + 64 + tid] = s;
    }
    __syncthreads();

    // L1 (edge): info[:, :5] -> h1 (A cols 0..63); cs_next -> cs2[0..63]
    layer_run<5, 64, 4>(sm, A, 64, A, sm + S_CS2 + 64, sm + S_CS2,
                        sm + S_W1s, sm + S_W1s128, sm + S_B1,
                        0, tid, lane, n, q, peer, smbase);

    // L2: h75 (A cols 0..74) -> h2 (Bb cols 0..63); cs_next -> cs3
    layer_run<75, 64, 4>(sm, A, 0, Bb, sm + S_CS2, sm + S_CS3,
                         sm + S_W2s, sm + S_W2s, sm + S_B2,
                         1, tid, lane, n, q, peer, smbase);

    // L3: h2 -> h3 (A cols 0..31); cs_next -> cs4
    layer_run<64, 32, 2>(sm, Bb, 0, A, sm + S_CS3, sm + S_CS4,
                         sm + S_W3s, sm + S_W3s, sm + S_B3,
                         0, tid, lane, n, q, peer, smbase);

    // L4: h3 -> h4 (Bb cols 0..15); cs_next -> cs5
    layer_run<32, 16, 1>(sm, A, 0, Bb, sm + S_CS4, sm + S_CS5,
                         sm + S_W4s, sm + S_W4s, sm + S_B4,
                         1, tid, lane, n, q, peer, smbase);

    // ---- heads on h4 (Bb cols 0..15; local csl = cs5) ----
    {
        float* base = sm + S_BASE;
        float* bp   = sm + S_BP;   // slot 0 free again
        if (tid < 8) {
            int j = tid >> 2, p = tid & 3;
            float s = 0.f;
            for (int k = p; k < 16; k += 4) s += sm[S_CS5 + k] * sm[S_WNs + k * 2 + j];
            s += __shfl_xor_sync(0xffu, s, 1);
            s += __shfl_xor_sync(0xffu, s, 2);
            if (p == 0) bp[j] = s;
        }
        CLUSTER_ARRIVE();
        float accn = 0.f;
        if (q < 2) {
            const float* srow = Bb + n * STRIDE;
            #pragma unroll
            for (int k = 0; k < 16; k++) accn += srow[k] * sm[S_WNs + k * 2 + q];
        }
        CLUSTER_WAIT();
        if (tid < 2) {
            uint32_t la = smbase + (uint32_t)(S_BP + tid) * 4u;
            base[tid] = sm[S_BN + tid] + bp[tid] + ld_peer_f32(la, peer);
        } else if (tid >= 32 && tid < 48) {
            // pull peer's h4 colsum for the scene head
            uint32_t la = smbase + (uint32_t)(S_CS5 + tid - 32) * 4u;
            sm[S_SCENEB + tid - 32] = ld_peer_f32(la, peer);
        }
        __syncthreads();
        if (q < 2) {
            size_t gnode = (size_t)b * NODES + rank * LOCALN + n;
            out[64 + gnode * 2 + q] = base[q] - accn;
        }

        // scene head: rank 0, thread 0
        if (rank == 0 && tid == 0) {
            float scene[16];
            #pragma unroll
            for (int k = 0; k < 16; k++)
                scene[k] = (sm[S_CS5 + k] + sm[S_SCENEB + k]) * (1.0f / NODES);
            float z = sm[S_BG2];
            #pragma unroll
            for (int o = 0; o < 8; o++) {
                float g = sm[S_BG1 + o];
                #pragma unroll
                for (int k = 0; k < 16; k++) g += scene[k] * sm[S_WG1 + k * 8 + o];
                g = fmaxf(g, 0.f);
                z += g * sm[S_WG2 + o];
            }
            out[b] = 1.0f / (1.0f + expf(-z));
        }
    }

    // no CTA may exit while the peer might still read its smem via DSMEM
    CLUSTER_ARRIVE();
    CLUSTER_WAIT();
}

extern "C" void kernel_launch(void* const* d_in, const int* in_sizes, int n_in,
                              void* d_out, int out_size) {
    const float* obj = (const float*)d_in[0];
    const float* W1  = (const float*)d_in[1];
    const float* b1  = (const float*)d_in[2];
    const float* W2  = (const float*)d_in[3];
    const float* b2  = (const float*)d_in[4];
    const float* W3  = (const float*)d_in[5];
    const float* b3  = (const float*)d_in[6];
    const float* W4  = (const float*)d_in[7];
    const float* b4  = (const float*)d_in[8];
    const float* Wn  = (const float*)d_in[9];
    const float* bn  = (const float*)d_in[10];
    const float* Wg1 = (const float*)d_in[11];
    const float* bg1 = (const float*)d_in[12];
    const float* Wg2 = (const float*)d_in[13];
    const float* bg2 = (const float*)d_in[14];
    // d_in[15]=src, d_in[16]=dst: complete graph, exploited analytically.

    cudaFuncSetAttribute(gnn_scene_kernel,
                         cudaFuncAttributeMaxDynamicSharedMemorySize, SMEM_BYTES);
    gnn_scene_kernel<<<SCENES * 2, THREADS, SMEM_BYTES>>>(
        obj, W1, b1, W2, b2, W3, b3, W4, b4, Wn, bn, Wg1, bg1, Wg2, bg2,
        (float*)d_out);
}

// round 10
// speedup vs baseline: 1.3597x; 1.1205x over previous
#include <cuda_runtime.h>
#include <math.h>
#include <stdint.h>

// GNN on complete per-scene digraphs: B=64 scenes, N=128 nodes.
// segment_mean at node d = (scene_sum(h) - h[d]) / 127.
// R10 = R4 (best, 19.4us) + two surgical LSU/issue cuts:
//   (1) float4 srow loads (STRIDE=84, conflict-free)
//   (2) packed fma.rn.f32x2 node-term FMAs
// Everything else identical to R4: 2-CTA cluster/scene, 512 thr/CTA
// (8 thr/node, JT 8/8/4/2), separate colsum passes, pull-style bp exchange
// with ping-pong slots, base = bias + bp_local + bp_peer.

#define NODES    128
#define LOCALN   64
#define SCENES   64
#define THREADS  512
#define STRIDE   84          // 16B-aligned rows; float4 starts tile all banks
#define INV127   (1.0f/127.0f)

typedef unsigned long long u64;

// smem layout (float indices)
#define S_W1s    0            // 5*64  (W1/127)
#define S_W1s128 320          // 5*64  (W1*128/127)
#define S_B1     640          // 64
#define S_W2s    704          // 75*64
#define S_B2     5504         // 64
#define S_W3s    5568         // 64*32
#define S_B3     7616         // 32
#define S_W4s    7648         // 32*16
#define S_B4     8160         // 16
#define S_WNs    8176         // 16*2
#define S_BN     8208         // 2 (+2)
#define S_WG1    8212         // 16*8
#define S_BG1    8340         // 8
#define S_WG2    8348         // 8
#define S_BG2    8356         // 1 (+3)
#define S_A      8360         // 64*84
#define S_BUF    13736        // 64*84
#define S_CSL    19112        // 2 slots x 80 local colsums
#define S_BP     19272        // 2 slots x 64 base-partials
#define S_BASE   19400        // 64
#define S_SCENEB 19464        // 16
#define S_PART   19480        // 512
#define S_TOT    19992
#define SMEM_BYTES (S_TOT * 4)   // 79968 B

__device__ __forceinline__ uint32_t smem_u32(const void* p) {
    uint32_t a;
    asm("{ .reg .u64 t; cvta.to.shared.u64 t, %1; cvt.u32.u64 %0, t; }"
        : "=r"(a) : "l"(p));
    return a;
}
__device__ __forceinline__ float ld_peer_f32(uint32_t la, uint32_t peer) {
    uint32_t ra;
    asm("mapa.shared::cluster.u32 %0, %1, %2;" : "=r"(ra) : "r"(la), "r"(peer));
    float v;
    asm volatile("ld.shared::cluster.f32 %0, [%1];" : "=f"(v) : "r"(ra));
    return v;
}
#define CLUSTER_ARRIVE() asm volatile("barrier.cluster.arrive.aligned;" ::: "memory")
#define CLUSTER_WAIT()   asm volatile("barrier.cluster.wait.aligned;"   ::: "memory")

// ---- packed f32x2 helpers ----
__device__ __forceinline__ u64 pack2(float lo, float hi) {
    u64 r; asm("mov.b64 %0, {%1, %2};" : "=l"(r) : "f"(lo), "f"(hi)); return r;
}
__device__ __forceinline__ void unpack2(u64 v, float& lo, float& hi) {
    asm("mov.b64 {%0, %1}, %2;" : "=f"(lo), "=f"(hi) : "l"(v));
}
__device__ __forceinline__ u64 fma2(u64 a, u64 b, u64 c) {
    u64 r; asm("fma.rn.f32x2 %0, %1, %2, %3;" : "=l"(r) : "l"(a), "l"(b), "l"(c)); return r;
}

// local column sum over LOCALN rows of C columns at 'off' -> dst[C].
// All THREADS reach the barriers. Ends synced (csl visible).
template<int C>
__device__ __forceinline__ void colsum_local(const float* __restrict__ S, int off,
                                             float* __restrict__ dst,
                                             float* __restrict__ part, int tid) {
    constexpr int P    = (THREADS / C) < 8 ? (THREADS / C) : 8;
    constexpr int ROWS = (LOCALN + P - 1) / P;
    if (tid < C * P) {
        int c = tid % C, p = tid / C;
        int r0 = p * ROWS;
        int r1 = (r0 + ROWS < LOCALN) ? (r0 + ROWS) : LOCALN;
        float s = 0.f;
        for (int r = r0; r < r1; r++) s += S[r * STRIDE + off + c];
        part[p * C + c] = s;
    }
    __syncthreads();
    if (tid < C) {
        float s = 0.f;
        #pragma unroll
        for (int p = 0; p < P; p++) s += part[p * C + tid];
        dst[tid] = s;
    }
    __syncthreads();
}

// one k-step of the packed node term
template<int OUT, int JT>
__device__ __forceinline__ void nt_step(float a, const float* __restrict__ Ws,
                                        int k, int j0, u64* acc2) {
    u64 aa = pack2(a, a);
    if constexpr (JT == 8) {
        const ulonglong2* wr = reinterpret_cast<const ulonglong2*>(Ws + k * OUT + j0);
        ulonglong2 w0 = wr[0], w1 = wr[1];
        acc2[0] = fma2(aa, w0.x, acc2[0]);
        acc2[1] = fma2(aa, w0.y, acc2[1]);
        acc2[2] = fma2(aa, w1.x, acc2[2]);
        acc2[3] = fma2(aa, w1.y, acc2[3]);
    } else if constexpr (JT == 4) {
        ulonglong2 w = *reinterpret_cast<const ulonglong2*>(Ws + k * OUT + j0);
        acc2[0] = fma2(aa, w.x, acc2[0]);
        acc2[1] = fma2(aa, w.y, acc2[1]);
    } else {
        u64 w = *reinterpret_cast<const u64*>(Ws + k * OUT + j0);
        acc2[0] = fma2(aa, w, acc2[0]);
    }
}

// node term with float4 srow loads: acc2 covers columns j0..j0+JT-1
template<int IN, int OUT, int JT>
__device__ __forceinline__ void nodeterm2(const float* __restrict__ S, int soff,
                                          const float* __restrict__ Ws,
                                          u64* __restrict__ acc2, int n, int j0) {
    #pragma unroll
    for (int v = 0; v < JT / 2; v++) acc2[v] = 0ull;
    const float* srow = S + n * STRIDE + soff;
    constexpr int KB = IN / 4;
    const float4* s4 = reinterpret_cast<const float4*>(srow);
    for (int kb = 0; kb < KB; kb++) {
        float4 a4 = s4[kb];
        nt_step<OUT, JT>(a4.x, Ws, 4 * kb + 0, j0, acc2);
        nt_step<OUT, JT>(a4.y, Ws, 4 * kb + 1, j0, acc2);
        nt_step<OUT, JT>(a4.z, Ws, 4 * kb + 2, j0, acc2);
        nt_step<OUT, JT>(a4.w, Ws, 4 * kb + 3, j0, acc2);
    }
    #pragma unroll
    for (int k = KB * 4; k < IN; k++)
        nt_step<OUT, JT>(srow[k], Ws, k, j0, acc2);
}

// One GCN layer, R4 sequence:
//   colsum_local -> basepart(bp slot) -> ARRIVE -> nodeterm -> WAIT ->
//   combine(base = bias + bp + peer bp) -> sync -> emit -> sync
template<int IN, int OUT, int JT>
__device__ __forceinline__ void layer_run(
    float* __restrict__ sm, const float* __restrict__ Ssrc, int soff,
    float* __restrict__ D, int csoff,
    const float* __restrict__ Wb, const float* __restrict__ Wn_,
    const float* __restrict__ bias,
    int slot, int tid, int n, int q, uint32_t peer, uint32_t smbase)
{
    float* base = sm + S_BASE;
    float* csl  = sm + S_CSL + slot * 80;
    float* bp   = sm + S_BP  + slot * 64;

    colsum_local<IN>(Ssrc, csoff, csl, sm + S_PART, tid);

    // base-partial on LOCAL colsum: 4 threads per output column
    if (tid < 4 * OUT) {
        const int j = tid >> 2, p = tid & 3;
        float s = 0.f;
        for (int k = p; k < IN; k += 4) s += csl[k] * Wb[k * OUT + j];
        s += __shfl_xor_sync(0xffffffffu, s, 1);
        s += __shfl_xor_sync(0xffffffffu, s, 2);
        if (p == 0) bp[j] = s;
    }
    CLUSTER_ARRIVE();

    const int j0 = q * JT;
    u64 acc2[JT / 2];
    nodeterm2<IN, OUT, JT>(Ssrc, soff, Wn_, acc2, n, j0);

    CLUSTER_WAIT();

    if (tid < OUT) {
        uint32_t la = smbase + (uint32_t)(S_BP + slot * 64 + tid) * 4u;
        base[tid] = bias[tid] + bp[tid] + ld_peer_f32(la, peer);
    }
    __syncthreads();

    // emit: relu(base - acc) -> D
    float* drow = D + n * STRIDE + j0;
    if constexpr (JT == 8) {
        float r[8];
        #pragma unroll
        for (int v = 0; v < 4; v++) {
            float lo, hi; unpack2(acc2[v], lo, hi);
            r[2*v]   = fmaxf(base[j0 + 2*v]     - lo, 0.f);
            r[2*v+1] = fmaxf(base[j0 + 2*v + 1] - hi, 0.f);
        }
        reinterpret_cast<float4*>(drow)[0] = make_float4(r[0], r[1], r[2], r[3]);
        reinterpret_cast<float4*>(drow)[1] = make_float4(r[4], r[5], r[6], r[7]);
    } else if constexpr (JT == 4) {
        float l0, h0, l1, h1;
        unpack2(acc2[0], l0, h0); unpack2(acc2[1], l1, h1);
        *reinterpret_cast<float4*>(drow) = make_float4(
            fmaxf(base[j0 + 0] - l0, 0.f), fmaxf(base[j0 + 1] - h0, 0.f),
            fmaxf(base[j0 + 2] - l1, 0.f), fmaxf(base[j0 + 3] - h1, 0.f));
    } else {
        float l0, h0; unpack2(acc2[0], l0, h0);
        *reinterpret_cast<float2*>(drow) = make_float2(
            fmaxf(base[j0 + 0] - l0, 0.f), fmaxf(base[j0 + 1] - h0, 0.f));
    }
    __syncthreads();
}

__global__ __launch_bounds__(THREADS, 1) __cluster_dims__(2, 1, 1)
void gnn_scene_kernel(const float* __restrict__ obj_info,
                      const float* __restrict__ W1, const float* __restrict__ b1,
                      const float* __restrict__ W2, const float* __restrict__ b2,
                      const float* __restrict__ W3, const float* __restrict__ b3,
                      const float* __restrict__ W4, const float* __restrict__ b4,
                      const float* __restrict__ Wn, const float* __restrict__ bn,
                      const float* __restrict__ Wg1, const float* __restrict__ bg1,
                      const float* __restrict__ Wg2, const float* __restrict__ bg2,
                      float* __restrict__ out) {
    extern __shared__ float sm[];
    const int tid  = threadIdx.x;
    const int b    = blockIdx.x >> 1;
    const uint32_t rank = blockIdx.x & 1;
    const uint32_t peer = rank ^ 1u;
    const int n = tid & (LOCALN - 1);   // local node 0..63
    const int q = tid >> 6;             // 0..7
    const uint32_t smbase = smem_u32(sm);

    // ---- load + prescale weights ----
    for (int i = tid; i < 5 * 64; i += THREADS) {
        float w = W1[i];
        sm[S_W1s + i]    = w * INV127;
        sm[S_W1s128 + i] = w * (128.0f * INV127);
    }
    #define CPYS(dst, src, cnt) \
        for (int i = tid; i < (cnt); i += THREADS) sm[(dst) + i] = src[i] * INV127;
    #define CPY(dst, src, cnt) \
        for (int i = tid; i < (cnt); i += THREADS) sm[(dst) + i] = src[i];
    CPYS(S_W2s, W2, 75*64);  CPY(S_B2, b2, 64);
    CPYS(S_W3s, W3, 64*32);  CPY(S_B3, b3, 32);
    CPYS(S_W4s, W4, 32*16);  CPY(S_B4, b4, 16);
    CPYS(S_WNs, Wn, 16*2);   CPY(S_BN, bn, 2);
    CPY(S_B1, b1, 64);
    CPY(S_WG1, Wg1, 16*8);   CPY(S_BG1, bg1, 8);
    CPY(S_WG2, Wg2, 8);      CPY(S_BG2, bg2, 1);
    #undef CPYS
    #undef CPY

    // ---- load this CTA's 64 rows of info[b] into A cols 64..74 ----
    {
        const float* src = obj_info + ((size_t)b * NODES + rank * LOCALN) * 11;
        for (int i = tid; i < LOCALN * 11; i += THREADS) {
            int r = i / 11, c = i % 11;
            sm[S_A + r * STRIDE + 64 + c] = src[i];
        }
    }
    __syncthreads();

    float* A  = sm + S_A;
    float* Bb = sm + S_BUF;

    // L1 (edge): info (A cols 64..74, first 5) -> h1 (A cols 0..63)
    layer_run<5, 64, 8>(sm, A, 64, A, 64,
                        sm + S_W1s, sm + S_W1s128, sm + S_B1,
                        0, tid, n, q, peer, smbase);

    // L2: h75 (A cols 0..74) -> h2 (Bb cols 0..63)
    layer_run<75, 64, 8>(sm, A, 0, Bb, 0,
                         sm + S_W2s, sm + S_W2s, sm + S_B2,
                         1, tid, n, q, peer, smbase);

    // L3: h2 -> h3 (A cols 0..31)
    layer_run<64, 32, 4>(sm, Bb, 0, A, 0,
                         sm + S_W3s, sm + S_W3s, sm + S_B3,
                         0, tid, n, q, peer, smbase);

    // L4: h3 -> h4 (Bb cols 0..15)
    layer_run<32, 16, 2>(sm, A, 0, Bb, 0,
                         sm + S_W4s, sm + S_W4s, sm + S_B4,
                         1, tid, n, q, peer, smbase);

    // ---- heads on h4 (Bb cols 0..15) ----
    {
        float* base = sm + S_BASE;
        float* csl  = sm + S_CSL;      // slot 0
        float* bp   = sm + S_BP;       // slot 0
        colsum_local<16>(Bb, 0, csl, sm + S_PART, tid);

        if (tid < 8) {
            int j = tid >> 2, p = tid & 3;
            float s = 0.f;
            for (int k = p; k < 16; k += 4) s += csl[k] * sm[S_WNs + k * 2 + j];
            s += __shfl_xor_sync(0xffu, s, 1);
            s += __shfl_xor_sync(0xffu, s, 2);
            if (p == 0) bp[j] = s;
        }
        CLUSTER_ARRIVE();
        float accn = 0.f;
        if (q < 2) {
            const float* srow = Bb + n * STRIDE;
            #pragma unroll
            for (int k = 0; k < 16; k++) accn += srow[k] * sm[S_WNs + k * 2 + q];
        }
        CLUSTER_WAIT();
        if (tid < 2) {
            uint32_t la = smbase + (uint32_t)(S_BP + tid) * 4u;
            base[tid] = sm[S_BN + tid] + bp[tid] + ld_peer_f32(la, peer);
        } else if (tid >= 32 && tid < 48) {
            uint32_t la = smbase + (uint32_t)(S_CSL + tid - 32) * 4u;
            sm[S_SCENEB + tid - 32] = ld_peer_f32(la, peer);
        }
        __syncthreads();
        if (q < 2) {
            size_t gnode = (size_t)b * NODES + rank * LOCALN + n;
            out[64 + gnode * 2 + q] = base[q] - accn;
        }

        // scene head: rank 0, thread 0
        if (rank == 0 && tid == 0) {
            float scene[16];
            #pragma unroll
            for (int k = 0; k < 16; k++)
                scene[k] = (csl[k] + sm[S_SCENEB + k]) * (1.0f / NODES);
            float z = sm[S_BG2];
            #pragma unroll
            for (int o = 0; o < 8; o++) {
                float g = sm[S_BG1 + o];
                #pragma unroll
                for (int k = 0; k < 16; k++) g += scene[k] * sm[S_WG1 + k * 8 + o];
                g = fmaxf(g, 0.f);
                z += g * sm[S_WG2 + o];
            }
            out[b] = 1.0f / (1.0f + expf(-z));
        }
    }

    // no CTA may exit while the peer might still read its smem via DSMEM
    CLUSTER_ARRIVE();
    CLUSTER_WAIT();
}

extern "C" void kernel_launch(void* const* d_in, const int* in_sizes, int n_in,
                              void* d_out, int out_size) {
    const float* obj = (const float*)d_in[0];
    const float* W1  = (const float*)d_in[1];
    const float* b1  = (const float*)d_in[2];
    const float* W2  = (const float*)d_in[3];
    const float* b2  = (const float*)d_in[4];
    const float* W3  = (const float*)d_in[5];
    const float* b3  = (const float*)d_in[6];
    const float* W4  = (const float*)d_in[7];
    const float* b4  = (const float*)d_in[8];
    const float* Wn  = (const float*)d_in[9];
    const float* bn  = (const float*)d_in[10];
    const float* Wg1 = (const float*)d_in[11];
    const float* bg1 = (const float*)d_in[12];
    const float* Wg2 = (const float*)d_in[13];
    const float* bg2 = (const float*)d_in[14];
    // d_in[15]=src, d_in[16]=dst: complete graph, exploited analytically.

    cudaFuncSetAttribute(gnn_scene_kernel,
                         cudaFuncAttributeMaxDynamicSharedMemorySize, SMEM_BYTES);
    gnn_scene_kernel<<<SCENES * 2, THREADS, SMEM_BYTES>>>(
        obj, W1, b1, W2, b2, W3, b3, W4, b4, Wn, bn, Wg1, bg1, Wg2, bg2,
        (float*)d_out);
}